// round 16
// baseline (speedup 1.0000x reference)
#include <cuda_runtime.h>
#include <cuda_bf16.h>
#include <cuda_fp16.h>
#include <cstdint>
#include <math.h>

#define LQ   256
#define DHH  64
#define NH   8
#define NM   64
#define NSL  (NH*NM)   // 512
#define DMOD 512
#define NTOK (NM*LQ)   // 16384

// ---------------- scratch -------------
__device__ float g_z1[NSL * LQ * DHH];       // [hm][i][d]
__device__ float g_z2[LQ * NH * DHH];        // [i][h][d]
__device__ float g_invl[NSL * LQ];           // [hm][i]

__device__ __half g_x16[NTOK * DMOD];
__device__ __half g_w16[3 * DMOD * DMOD];
__device__ __half g_q16[NSL * LQ * DHH];     // [hm][i][d]
__device__ __half g_k16[NSL * LQ * DHH];
__device__ __half g_v16[NSL * LQ * DHH];
__device__ __half g_ak16[LQ * LQ * DHH];     // [i][j][d]
__device__ __half g_av16[LQ * LQ * DHH];
__device__ __half g_e16[NSL * LQ * LQ];      // e2 fp16 [hm][i][j]
__device__ __half g_a16[NSL * LQ * LQ];      // unnormalized p fp16 [hm][i][j]

// ========================= helpers ==================================
__device__ __forceinline__ uint32_t smem_to_u32(const void* p) {
    uint32_t a;
    asm("{ .reg .u64 t; cvta.to.shared.u64 t, %1; cvt.u32.u64 %0, t; }"
        : "=r"(a) : "l"(p));
    return a;
}
__device__ __forceinline__ void ldsm_x4(uint32_t addr, uint32_t* r) {
    asm volatile("ldmatrix.sync.aligned.m8n8.x4.shared.b16 {%0,%1,%2,%3}, [%4];"
        : "=r"(r[0]), "=r"(r[1]), "=r"(r[2]), "=r"(r[3]) : "r"(addr));
}
__device__ __forceinline__ void ldsm_x4_t(uint32_t addr, uint32_t* r) {
    asm volatile("ldmatrix.sync.aligned.m8n8.x4.trans.shared.b16 {%0,%1,%2,%3}, [%4];"
        : "=r"(r[0]), "=r"(r[1]), "=r"(r[2]), "=r"(r[3]) : "r"(addr));
}
__device__ __forceinline__ void mma_f16(float* c, const uint32_t* a,
                                        const uint32_t* b) {
    asm volatile(
        "mma.sync.aligned.m16n8k16.row.col.f32.f16.f16.f32 "
        "{%0,%1,%2,%3}, {%4,%5,%6,%7}, {%8,%9}, {%0,%1,%2,%3};"
        : "+f"(c[0]), "+f"(c[1]), "+f"(c[2]), "+f"(c[3])
        : "r"(a[0]), "r"(a[1]), "r"(a[2]), "r"(a[3]), "r"(b[0]), "r"(b[1]));
}
__device__ __forceinline__ uint32_t pack_f16(float a, float b) {
    __half2 h(__float2half(a), __float2half(b));
    return *(uint32_t*)&h;
}
__device__ __forceinline__ void cp16(uint32_t s, const void* g) {
    asm volatile("cp.async.cg.shared.global [%0], [%1], 16;"
                 :: "r"(s), "l"(g) : "memory");
}
#define CP_COMMIT() asm volatile("cp.async.commit_group;" ::: "memory")
#define CP_WAIT(n)  asm volatile("cp.async.wait_group %0;" :: "n"(n) : "memory")

// ============================================================================
// merged convert: all 6 tensors fp32 -> single fp16
// ============================================================================
struct SplitArgs {
    const float* src[6];
    __half* dst[6];
    int off[7];
};

__global__ __launch_bounds__(256) void split_all_kernel(SplitArgs a)
{
    int total = a.off[6];
    for (int idx = blockIdx.x * 256 + threadIdx.x; idx < total;
         idx += gridDim.x * 256) {
        int seg = 0;
#pragma unroll
        for (int s = 1; s < 6; s++) if (idx >= a.off[s]) seg = s;
        int li = idx - a.off[seg];
        float4 v = *(const float4*)&a.src[seg][li * 4];
        __half2 a01(__float2half(v.x), __float2half(v.y));
        __half2 a23(__float2half(v.z), __float2half(v.w));
        __half* dp = a.dst[seg];
        *(__half2*)&dp[li * 4]     = a01;
        *(__half2*)&dp[li * 4 + 2] = a23;
    }
}

// ============================================================================
// K1: projection GEMM, single-pass fp16. CTA 128x128, K=512 in 16 chunks.
// ============================================================================
#define PMAT  (128 * 80)      // 10240
#define PSTG  (2 * PMAT)      // 20480
#define P_TOT (2 * PSTG)      // 40960

__global__ __launch_bounds__(256) void proj_mma_kernel()
{
    extern __shared__ __align__(16) unsigned char dsm[];
    const uint32_t sb = smem_to_u32(dsm);

    const int tid = threadIdx.x, lane = tid & 31, wid = tid >> 5;
    const int t0 = blockIdx.x * 128;
    const int n0 = blockIdx.y * 128;
    const int sel = blockIdx.z;

    const __half* A = g_x16;
    const __half* B = g_w16 + sel * DMOD * DMOD;
    __half* outp = (sel == 0) ? g_q16 : ((sel == 1) ? g_k16 : g_v16);

    const int wm = (wid & 3) * 32;
    const int wn = (wid >> 2) * 64;
    const int lr  = (tid >> 2);
    const int seg = tid & 3;

    auto stage_load = [&](int ch, int st) {
        const int k0 = ch * 32;
        uint32_t s0 = sb + st * PSTG;
#pragma unroll
        for (int l = 0; l < 4; l++) {
            int mat = l >> 1;
            int r = (l & 1) * 64 + lr;
            const __half* gp = mat ? B : A;
            int row = (mat ? n0 : t0) + r;
            cp16(s0 + mat * PMAT + r * 80 + seg * 16,
                 &gp[row * DMOD + k0 + seg * 8]);
        }
    };

    float acc[2][8][4];
#pragma unroll
    for (int a = 0; a < 2; a++)
#pragma unroll
        for (int b = 0; b < 8; b++)
#pragma unroll
            for (int c = 0; c < 4; c++) acc[a][b][c] = 0.f;

    stage_load(0, 0);
    CP_COMMIT();

    for (int ch = 0; ch < 16; ch++) {
        const int st = ch & 1;
        if (ch + 1 < 16) { stage_load(ch + 1, st ^ 1); CP_COMMIT(); CP_WAIT(1); }
        else             { CP_WAIT(0); }
        __syncthreads();

        const uint32_t s0 = sb + st * PSTG;
#pragma unroll
        for (int s = 0; s < 2; s++) {
            uint32_t af[2][4];
#pragma unroll
            for (int mi = 0; mi < 2; mi++) {
                int row = wm + mi * 16 + (lane & 15);
                uint32_t ad = s0 + row * 80 + s * 32 + ((lane >> 4) & 1) * 16;
                ldsm_x4(ad, af[mi]);
            }
#pragma unroll
            for (int p = 0; p < 4; p++) {
                uint32_t bf[4];
                int row = wn + p * 16 + (lane & 7) + ((lane >> 4) & 1) * 8;
                uint32_t bd = s0 + PMAT + row * 80 + s * 32 + ((lane >> 3) & 1) * 16;
                ldsm_x4(bd, bf);
#pragma unroll
                for (int mi = 0; mi < 2; mi++)
#pragma unroll
                    for (int su = 0; su < 2; su++)
                        mma_f16(acc[mi][p * 2 + su], af[mi], &bf[su * 2]);
            }
        }
        __syncthreads();
    }

#pragma unroll
    for (int mi = 0; mi < 2; mi++)
#pragma unroll
        for (int ni = 0; ni < 8; ni++) {
            int e = n0 + wn + ni * 8 + (lane & 3) * 2;
            int h = e >> 6, d = e & 63;
#pragma unroll
            for (int rr = 0; rr < 2; rr++) {
                int t = t0 + wm + mi * 16 + (lane >> 2) + rr * 8;
                int m = t >> 8, i = t & 255;
                int idx = ((h * NM + m) * LQ + i) * DHH + d;
                *(uint32_t*)&outp[idx] =
                    pack_f16(acc[mi][ni][rr * 2 + 0], acc[mi][ni][rr * 2 + 1]);
            }
        }
}

// ============================================================================
// K2: e2 fp16 single-pass, output layout [hm][i][j]. CTA 128x128, K=64.
// ============================================================================
#define E4_ASZ (128 * 144)    // 18432
#define E4_TOT (2 * E4_ASZ)   // 36864

__global__ __launch_bounds__(256) void e2_mma_kernel()
{
    extern __shared__ __align__(16) unsigned char dsm[];
    const uint32_t sb = smem_to_u32(dsm);

    const int tid = threadIdx.x, lane = tid & 31, wid = tid >> 5;
    const int hm0 = blockIdx.x * 128;
    const int j0  = blockIdx.y * 128;
    const int i   = blockIdx.z;
    const int wm = (wid & 3) * 32;
    const int wn = (wid >> 2) * 64;

#pragma unroll
    for (int l = 0; l < 4; l++) {
        int id = tid + l * 256;
        int r = id >> 3, c = id & 7;
        cp16(sb + r * 144 + c * 16, &g_q16[((hm0 + r) * LQ + i) * DHH + c * 8]);
        cp16(sb + E4_ASZ + r * 144 + c * 16,
             &g_ak16[(i * LQ + j0 + r) * DHH + c * 8]);
    }
    CP_COMMIT();
    CP_WAIT(0);
    __syncthreads();

    float acc[2][8][4];
#pragma unroll
    for (int a = 0; a < 2; a++)
#pragma unroll
        for (int b = 0; b < 8; b++)
#pragma unroll
            for (int c = 0; c < 4; c++) acc[a][b][c] = 0.f;

#pragma unroll
    for (int s = 0; s < 4; s++) {
        uint32_t af[2][4];
#pragma unroll
        for (int mi = 0; mi < 2; mi++) {
            uint32_t ad = sb + (wm + mi * 16 + (lane & 15)) * 144 +
                          s * 32 + ((lane >> 4) & 1) * 16;
            ldsm_x4(ad, af[mi]);
        }
#pragma unroll
        for (int p = 0; p < 4; p++) {
            uint32_t bf[4];
            uint32_t bd = sb + E4_ASZ +
                (wn + p * 16 + (lane & 7) + ((lane >> 4) & 1) * 8) * 144 +
                s * 32 + ((lane >> 3) & 1) * 16;
            ldsm_x4(bd, bf);
#pragma unroll
            for (int mi = 0; mi < 2; mi++)
#pragma unroll
                for (int su = 0; su < 2; su++)
                    mma_f16(acc[mi][p * 2 + su], af[mi], &bf[su * 2]);
        }
    }

#pragma unroll
    for (int mi = 0; mi < 2; mi++)
#pragma unroll
        for (int ni = 0; ni < 8; ni++) {
            int j = j0 + wn + ni * 8 + (lane & 3) * 2;
#pragma unroll
            for (int rr = 0; rr < 2; rr++) {
                int hm = hm0 + wm + mi * 16 + (lane >> 2) + rr * 8;
                *(uint32_t*)&g_e16[(hm * LQ + i) * LQ + j] =
                    pack_f16(acc[mi][ni][rr * 2 + 0], acc[mi][ni][rr * 2 + 1]);
            }
        }
}

// ============================================================================
// K3: fused attention; e2 staged via cp.async and consumed via ldsm fragments
// stage: K 9216 | V 9216 | E 18432 = 36864, x2 + Q 18432 = 92160
// ============================================================================
#define A4_KSZ  (64 * 144)            // 9216
#define A4_ESZ  (128 * 144)           // 18432
#define A4_STG  (2 * A4_KSZ + A4_ESZ) // 36864
#define A4_Q    (2 * A4_STG)          // 73728
#define A4_QSZ  (128 * 144)           // 18432
#define A4_TOT  (A4_Q + A4_QSZ)       // 92160

__global__ __launch_bounds__(256) void attn_mma_kernel()
{
    extern __shared__ __align__(16) unsigned char dsm[];
    const uint32_t sb = smem_to_u32(dsm);
    const int tid = threadIdx.x, lane = tid & 31, wid = tid >> 5;
    const int i0 = blockIdx.x * 128;
    const int hm = blockIdx.y;
    const int wm = wid * 16;
    const int gr = lane >> 2, qd = lane & 3;

    auto load_stage = [&](int jc, int st) {
        uint32_t s0 = sb + st * A4_STG;
#pragma unroll
        for (int l = 0; l < 2; l++) {
            int id = tid + l * 256;
            int r = id >> 3, c = id & 7;
            int gk = (hm * LQ + jc * 64 + r) * DHH + c * 8;
            cp16(s0 + r * 144 + c * 16, &g_k16[gk]);
            cp16(s0 + A4_KSZ + r * 144 + c * 16, &g_v16[gk]);
        }
#pragma unroll
        for (int l = 0; l < 4; l++) {
            int id = tid + l * 256;
            int r = id >> 3, c = id & 7;
            cp16(s0 + 2 * A4_KSZ + r * 144 + c * 16,
                 &g_e16[(hm * LQ + i0 + r) * LQ + jc * 64 + c * 8]);
        }
    };

    // Q resident
#pragma unroll
    for (int l = 0; l < 4; l++) {
        int id = tid + l * 256;
        int r = id >> 3, c = id & 7;
        cp16(sb + A4_Q + r * 144 + c * 16,
             &g_q16[(hm * LQ + i0 + r) * DHH + c * 8]);
    }
    CP_COMMIT();
    load_stage(0, 0);
    CP_COMMIT();

    float accz[8][4];
#pragma unroll
    for (int b = 0; b < 8; b++)
#pragma unroll
        for (int c = 0; c < 4; c++) accz[b][c] = 0.f;
    float rsum[2] = {0.f, 0.f};

    for (int jc = 0; jc < 4; jc++) {
        const int st = jc & 1;
        __syncthreads();
        if (jc < 3) { load_stage(jc + 1, st ^ 1); CP_COMMIT(); CP_WAIT(1); }
        else        { CP_WAIT(0); }
        __syncthreads();

        const uint32_t s0 = sb + st * A4_STG;

        // ---- scores: e1 = q k^T ----
        float acc[8][4];
#pragma unroll
        for (int b = 0; b < 8; b++)
#pragma unroll
            for (int c = 0; c < 4; c++) acc[b][c] = 0.f;

#pragma unroll
        for (int s = 0; s < 4; s++) {
            uint32_t af[4];
            uint32_t ad = sb + A4_Q + (wm + (lane & 15)) * 144 +
                          s * 32 + ((lane >> 4) & 1) * 16;
            ldsm_x4(ad, af);
#pragma unroll
            for (int p = 0; p < 4; p++) {
                uint32_t bf[4];
                uint32_t bd = s0 + (p * 16 + (lane & 7) + ((lane >> 4) & 1) * 8) * 144 +
                              s * 32 + ((lane >> 3) & 1) * 16;
                ldsm_x4(bd, bf);
#pragma unroll
                for (int su = 0; su < 2; su++)
                    mma_f16(acc[p * 2 + su], af, &bf[su * 2]);
            }
        }

        // ---- + e2 via fragment-aligned ldsm (A-frag layout == C layout) ----
#pragma unroll
        for (int s = 0; s < 4; s++) {
            uint32_t ef[4];
            uint32_t ed = s0 + 2 * A4_KSZ + (wm + (lane & 15)) * 144 +
                          s * 32 + ((lane >> 4) & 1) * 16;
            ldsm_x4(ed, ef);
            __half2 e0 = *(__half2*)&ef[0];
            __half2 e1 = *(__half2*)&ef[1];
            __half2 e2 = *(__half2*)&ef[2];
            __half2 e3 = *(__half2*)&ef[3];
            acc[2 * s][0]     += __half2float(e0.x);
            acc[2 * s][1]     += __half2float(e0.y);
            acc[2 * s][2]     += __half2float(e1.x);
            acc[2 * s][3]     += __half2float(e1.y);
            acc[2 * s + 1][0] += __half2float(e2.x);
            acc[2 * s + 1][1] += __half2float(e2.y);
            acc[2 * s + 1][2] += __half2float(e3.x);
            acc[2 * s + 1][3] += __half2float(e3.y);
        }

        // ---- scale, exp, rowsum, pack p fp16 ----
        uint32_t pf[8][2];
        {
            int ir0 = i0 + wm + gr;
#pragma unroll
            for (int ni = 0; ni < 8; ni++) {
                int col = jc * 64 + ni * 8 + qd * 2;
                float e0 = __expf(acc[ni][0] * 0.125f);
                float e1 = __expf(acc[ni][1] * 0.125f);
                float e2v = __expf(acc[ni][2] * 0.125f);
                float e3 = __expf(acc[ni][3] * 0.125f);
                rsum[0] += e0 + e1;
                rsum[1] += e2v + e3;
                uint32_t p01 = pack_f16(e0, e1);
                uint32_t p23 = pack_f16(e2v, e3);
                pf[ni][0] = p01; pf[ni][1] = p23;
                *(uint32_t*)&g_a16[(hm * LQ + ir0) * LQ + col] = p01;
                *(uint32_t*)&g_a16[(hm * LQ + ir0 + 8) * LQ + col] = p23;
            }
        }

        // ---- z1 += p V ----
#pragma unroll
        for (int s = 0; s < 4; s++) {
            uint32_t Af[4] = {pf[2 * s][0], pf[2 * s][1],
                              pf[2 * s + 1][0], pf[2 * s + 1][1]};
#pragma unroll
            for (int p = 0; p < 4; p++) {
                uint32_t bf[4];
                uint32_t bd = s0 + A4_KSZ + (s * 16 + (lane & 15)) * 144 +
                              p * 32 + ((lane >> 4) & 1) * 16;
                ldsm_x4_t(bd, bf);
#pragma unroll
                for (int su = 0; su < 2; su++)
                    mma_f16(accz[p * 2 + su], Af, &bf[su * 2]);
            }
        }
    }

    // ---- finalize ----
    float inv[2];
#pragma unroll
    for (int rr = 0; rr < 2; rr++) {
        float r = rsum[rr];
        r += __shfl_xor_sync(0xffffffffu, r, 1);
        r += __shfl_xor_sync(0xffffffffu, r, 2);
        inv[rr] = 1.f / r;
    }
    if (qd == 0) {
#pragma unroll
        for (int rr = 0; rr < 2; rr++)
            g_invl[hm * LQ + i0 + wm + gr + rr * 8] = inv[rr];
    }
#pragma unroll
    for (int ni = 0; ni < 8; ni++)
#pragma unroll
        for (int rr = 0; rr < 2; rr++) {
            int ir = i0 + wm + gr + rr * 8;
            int d = ni * 8 + qd * 2;
            *(float2*)&g_z1[(hm * LQ + ir) * DHH + d] =
                make_float2(accz[ni][rr * 2 + 0] * inv[rr],
                            accz[ni][rr * 2 + 1] * inv[rr]);
        }
}

// ============================================================================
// K4: z2 via m-reduction first:  z2[i,h,d] = sum_j (sum_m alpha) aV[i,j,d]
// one CTA per i; stream-reduce g_a16 rows, tiny dot with smem aV.
// ============================================================================
#define Z6_AV   0                       // 256*128 = 32768
#define Z6_LINV 32768                   // 512*4   = 2048
#define Z6_PB   (32768 + 2048)          // 256*4   = 1024
#define Z6_PART (Z6_PB + 1024)          // 512*4   = 2048
#define Z6_TOT  (Z6_PART + 2048)        // 37888

__global__ __launch_bounds__(256) void z2_kernel()
{
    extern __shared__ __align__(16) unsigned char dsm[];
    const uint32_t sb = smem_to_u32(dsm);
    const int tid = threadIdx.x;
    const int i = blockIdx.x;
    __half* aVs  = (__half*)(dsm + Z6_AV);
    float*  linv = (float*)(dsm + Z6_LINV);
    float*  Pb   = (float*)(dsm + Z6_PB);
    float*  part = (float*)(dsm + Z6_PART);

    // aV[i]: 256 j x 64 d, row pitch 128 B
#pragma unroll
    for (int l = 0; l < 8; l++) {
        int id = tid + l * 256;
        int r = id >> 3, c = id & 7;
        cp16(sb + Z6_AV + r * 128 + c * 16, &g_av16[(i * LQ + r) * DHH + c * 8]);
    }
    CP_COMMIT();
    for (int hm = tid; hm < NSL; hm += 256)
        linv[hm] = g_invl[hm * LQ + i];
    CP_WAIT(0);
    __syncthreads();

    const int jp = tid & 127, mh = tid >> 7;   // j-pair, m-half
    const int jg = tid >> 6, dd = tid & 63;    // j-group, d

    for (int h = 0; h < NH; h++) {
        // reduce p over m (fp32, scaled by linv)
        float s0 = 0.f, s1 = 0.f;
        const __half* base = &g_a16[((h * NM + mh * 32) * LQ + i) * LQ + jp * 2];
#pragma unroll 8
        for (int m = 0; m < 32; m++) {
            __half2 v = *(const __half2*)(base + m * (LQ * LQ));
            float li = linv[h * NM + mh * 32 + m];
            s0 += __half2float(v.x) * li;
            s1 += __half2float(v.y) * li;
        }
        part[mh * 256 + jp * 2]     = s0;
        part[mh * 256 + jp * 2 + 1] = s1;
        __syncthreads();
        if (tid < 128) {
            Pb[jp * 2]     = part[jp * 2]     + part[256 + jp * 2];
            Pb[jp * 2 + 1] = part[jp * 2 + 1] + part[256 + jp * 2 + 1];
        }
        __syncthreads();
        // dot: z2[h][dd] = sum_j Pb[j] aVs[j][dd]
        float acc = 0.f;
#pragma unroll 16
        for (int j = 0; j < 64; j++) {
            int jj = jg * 64 + j;
            acc += Pb[jj] * __half2float(aVs[jj * 64 + dd]);
        }
        part[tid] = acc;
        __syncthreads();
        if (tid < 64) {
            float r = part[tid] + part[64 + tid] + part[128 + tid] + part[192 + tid];
            g_z2[(i * NH + h) * DHH + tid] = r;
        }
        __syncthreads();
    }
}

// =============================================================================
// K5: out
// =============================================================================
__global__ __launch_bounds__(256) void final_kernel(float* __restrict__ out)
{
    int g = blockIdx.x * 256 + threadIdx.x;
    int i = g >> 9;
    int rest = g & 511;
    int h = rest >> 6;
    int d = rest & 63;

    const float* zp = &g_z1[((h * NM) * LQ + i) * DHH + d];
    float s = g_z2[(i * NH + h) * DHH + d];
#pragma unroll 8
    for (int m = 0; m < 64; m++) s += zp[m * (LQ * DHH)];
    out[g] = s;
}

// =============================================================================
extern "C" void kernel_launch(void* const* d_in, const int* in_sizes, int n_in,
                              void* d_out, int out_size)
{
    const float* x  = (const float*)d_in[0];
    const float* Wq = (const float*)d_in[1];
    const float* Wk = (const float*)d_in[2];
    const float* Wv = (const float*)d_in[3];
    const float* aK = (const float*)d_in[4];
    const float* aV = (const float*)d_in[5];
    float* out = (float*)d_out;

    cudaFuncSetAttribute(proj_mma_kernel,
                         cudaFuncAttributeMaxDynamicSharedMemorySize, P_TOT);
    cudaFuncSetAttribute(e2_mma_kernel,
                         cudaFuncAttributeMaxDynamicSharedMemorySize, E4_TOT);
    cudaFuncSetAttribute(attn_mma_kernel,
                         cudaFuncAttributeMaxDynamicSharedMemorySize, A4_TOT);
    cudaFuncSetAttribute(z2_kernel,
                         cudaFuncAttributeMaxDynamicSharedMemorySize, Z6_TOT);

    void *x_p, *w_p, *ak_p, *av_p;
    cudaGetSymbolAddress(&x_p,  g_x16);
    cudaGetSymbolAddress(&w_p,  g_w16);
    cudaGetSymbolAddress(&ak_p, g_ak16);
    cudaGetSymbolAddress(&av_p, g_av16);

    SplitArgs sa;
    sa.src[0] = x;  sa.dst[0] = (__half*)x_p;
    sa.src[1] = Wq; sa.dst[1] = (__half*)w_p;
    sa.src[2] = Wk; sa.dst[2] = (__half*)w_p + DMOD * DMOD;
    sa.src[3] = Wv; sa.dst[3] = (__half*)w_p + 2 * DMOD * DMOD;
    sa.src[4] = aK; sa.dst[4] = (__half*)ak_p;
    sa.src[5] = aV; sa.dst[5] = (__half*)av_p;
    int nv[6] = {NTOK * DMOD / 4, DMOD * DMOD / 4, DMOD * DMOD / 4,
                 DMOD * DMOD / 4, LQ * LQ * DHH / 4, LQ * LQ * DHH / 4};
    sa.off[0] = 0;
    for (int s = 0; s < 6; s++) sa.off[s + 1] = sa.off[s] + nv[s];

    split_all_kernel<<<4096, 256>>>(sa);

    proj_mma_kernel<<<dim3(NTOK / 128, DMOD / 128, 3), 256, P_TOT>>>();
    e2_mma_kernel<<<dim3(4, 2, LQ), 256, E4_TOT>>>();
    attn_mma_kernel<<<dim3(2, NSL), 256, A4_TOT>>>();
    z2_kernel<<<LQ, 256, Z6_TOT>>>();
    final_kernel<<<512, 256>>>(out);
}